// round 16
// baseline (speedup 1.0000x reference)
#include <cuda_runtime.h>
#include <cuda_bf16.h>
#include <cstdint>
#include <math.h>

#define B_   8
#define T_   4096
#define C_   1024
#define K_   2048
#define NK_  2048
#define BT   (B_ * T_)
#define BK   (B_ * K_)

#define FLAG_CAP 4096
#define WIN      1e-3f      // candidate window: 2x max bf16 sim error, with margin
#define NCAND    8

// ---- scratch (__device__ globals: allocation-free) ----
__device__ float  g_score[BT];
__device__ float  g_invn[BT];
__device__ int    g_keep[BK];
__device__ int    g_nonkept[B_ * NK_];
__device__ int    g_keeprank[BT];
__device__ unsigned long long g_arg[BT];
__device__ int    g_icnt[BK];
__device__ int    g_off[BK];
__device__ int    g_members[BT];
__device__ int    g_flagcntb[B_];
__device__ int    g_flagtokb[B_][FLAG_CAP];
__device__ unsigned char g_flagn[B_][FLAG_CAP];
__device__ short  g_flagcand[B_][FLAG_CAP][NCAND];
__device__ __nv_bfloat16 g_xbf[(size_t)BT * C_];   // 64 MB normalized bf16 tokens

__device__ __forceinline__ unsigned int ordf(float f) {
    unsigned int u = __float_as_uint(f);
    return (u & 0x80000000u) ? ~u : (u | 0x80000000u);
}
__device__ __forceinline__ float iordf(unsigned int u) {
    return __uint_as_float((u & 0x80000000u) ? (u & 0x7FFFFFFFu) : ~u);
}

// =====================  async-copy / mma helpers  =====================
__device__ __forceinline__ uint32_t smem_u32(const void* p) {
    uint32_t a;
    asm("{ .reg .u64 t; cvta.to.shared.u64 t, %1; cvt.u32.u64 %0, t; }" : "=r"(a) : "l"(p));
    return a;
}
__device__ __forceinline__ void cp16(uint32_t dst, const void* src) {
    asm volatile("cp.async.cg.shared.global [%0], [%1], 16;" :: "r"(dst), "l"(src) : "memory");
}
__device__ __forceinline__ void cp_commit() { asm volatile("cp.async.commit_group;" ::: "memory"); }
__device__ __forceinline__ void cp_wait1()  { asm volatile("cp.async.wait_group 1;" ::: "memory"); }
__device__ __forceinline__ void cp_wait0()  { asm volatile("cp.async.wait_group 0;" ::: "memory"); }

#define LDSM_X4(r0, r1, r2, r3, addr) \
    asm volatile("ldmatrix.sync.aligned.m8n8.x4.shared.b16 {%0,%1,%2,%3}, [%4];" \
        : "=r"(r0), "=r"(r1), "=r"(r2), "=r"(r3) : "r"(addr))
#define MMA16816(c, a, b0, b1) \
    asm volatile("mma.sync.aligned.m16n8k16.row.col.f32.bf16.bf16.f32 " \
        "{%0,%1,%2,%3}, {%4,%5,%6,%7}, {%8,%9}, {%0,%1,%2,%3};" \
        : "+f"((c)[0]), "+f"((c)[1]), "+f"((c)[2]), "+f"((c)[3]) \
        : "r"((a)[0]), "r"((a)[1]), "r"((a)[2]), "r"((a)[3]), "r"(b0), "r"(b1))

// ---------------------------------------------------------------
// 1) fused: per-token L2 score + inverse norm + normalized bf16.
//    fp32 per-thread partial -> exact int64 fixed-point reduction.
// ---------------------------------------------------------------
__global__ void __launch_bounds__(256) scoreq_kernel(const float* __restrict__ x) {
    int tok = blockIdx.x;
    const float4* xp = (const float4*)(x + (size_t)tok * C_);
    float4 v = xp[threadIdx.x];          // 256 threads x 4 floats
    float p = fmaf(v.x, v.x, fmaf(v.y, v.y, fmaf(v.z, v.z, v.w * v.w)));
    long long q = __float2ll_rn(p * 16777216.0f);   // 2^24 fixed point
    #pragma unroll
    for (int o = 16; o; o >>= 1) q += __shfl_down_sync(0xffffffffu, q, o);
    __shared__ long long sm[8];
    __shared__ float binv;
    if ((threadIdx.x & 31) == 0) sm[threadIdx.x >> 5] = q;
    __syncthreads();
    if (threadIdx.x == 0) {
        long long tq = 0;
        #pragma unroll
        for (int i = 0; i < 8; i++) tq += sm[i];
        double ss = (double)tq * (1.0 / 16777216.0);
        float fs = (float)ss;
        if ((tok & (T_ - 1)) == 0) fs = 3.402823466e+38f;   // CLS protection
        g_score[tok] = fs;
        float invn = (float)(1.0 / (sqrt(ss) + 1e-12));
        g_invn[tok] = invn;
        binv = invn;
    }
    __syncthreads();
    float inv = binv;
    __nv_bfloat162 h0 = __halves2bfloat162(__float2bfloat16(v.x * inv),
                                           __float2bfloat16(v.y * inv));
    __nv_bfloat162 h1 = __halves2bfloat162(__float2bfloat16(v.z * inv),
                                           __float2bfloat16(v.w * inv));
    ((uint2*)(g_xbf + (size_t)tok * C_))[threadIdx.x] =
        make_uint2(*(unsigned int*)&h0, *(unsigned int*)&h1);
}

// ---------------------------------------------------------------
// 2) per-batch exact top-K via 64-bit radix select + ordered
//    compaction (keys unique -> exact bound; token-order output).
// ---------------------------------------------------------------
__global__ void __launch_bounds__(1024) topk_kernel() {
    int b = blockIdx.x, tid = threadIdx.x;
    __shared__ unsigned long long skey[T_];     // token-order keys, 32KB
    __shared__ int hist[4][256];                // sub-histograms, 4KB
    __shared__ int sscan[1024];
    __shared__ unsigned long long sh_pref, sh_bound;
    __shared__ int sh_r, sh_done;

    if (tid == 0) { g_flagcntb[b] = 0; sh_pref = 0ull; sh_r = K_; sh_done = 0; }
    #pragma unroll
    for (int j = 0; j < 4; j++) {
        int i = tid * 4 + j;
        skey[i] = ((unsigned long long)(~ordf(g_score[b * T_ + i])) << 32)
                | (unsigned int)i;
    }
    __syncthreads();

    // byte-wise descent from MSB
    unsigned long long hi_mask = 0ull;
    int hsub = (tid >> 5) & 3;
    for (int byte = 7; byte >= 0; byte--) {
        if (sh_done) break;                      // uniform (smem, post-sync)
        int shift = byte * 8;
        ((int*)hist)[tid] = 0;
        __syncthreads();
        unsigned long long pref = sh_pref;
        #pragma unroll
        for (int j = 0; j < 4; j++) {
            unsigned long long k = skey[tid * 4 + j];
            if ((k & hi_mask) == pref)
                atomicAdd(&hist[hsub][(int)((k >> shift) & 255)], 1);
        }
        __syncthreads();
        if (tid == 0) {
            int r = sh_r, cum = 0;
            for (int bin = 0; bin < 256; bin++) {
                int c = hist[0][bin] + hist[1][bin] + hist[2][bin] + hist[3][bin];
                if (cum + c >= r) {
                    if (cum + c == r) {
                        sh_bound = (bin == 255 && shift == 56)
                                 ? ~0ull
                                 : pref + ((unsigned long long)(bin + 1) << shift);
                        sh_done = 1;
                    } else {
                        sh_pref = pref | ((unsigned long long)bin << shift);
                        sh_r = r - cum;
                    }
                    break;
                }
                cum += c;
            }
        }
        hi_mask |= (0xFFull << shift);
        __syncthreads();
    }
    if (tid == 0 && !sh_done) sh_bound = sh_pref + 1ull;  // exact key (unique)
    __syncthreads();
    unsigned long long bound = sh_bound;

    // token-order compaction
    int cnt = 0;
    #pragma unroll
    for (int j = 0; j < 4; j++) cnt += (skey[tid * 4 + j] < bound) ? 1 : 0;
    sscan[tid] = cnt;
    __syncthreads();
    for (int d = 1; d < 1024; d <<= 1) {
        int v = sscan[tid];
        int add = (tid >= d) ? sscan[tid - d] : 0;
        __syncthreads();
        sscan[tid] = v + add;
        __syncthreads();
    }
    int kpos = sscan[tid] - cnt;                 // keeps strictly before my tokens
    #pragma unroll
    for (int j = 0; j < 4; j++) {
        int i = tid * 4 + j;
        if (skey[i] < bound) {
            g_keep[b * K_ + kpos] = i;
            g_keeprank[b * T_ + i] = kpos;
            kpos++;
        } else {
            g_nonkept[b * NK_ + (i - kpos)] = i;
            g_keeprank[b * T_ + i] = -1;
        }
    }
}

// ---------------------------------------------------------------
// 3) bf16 mma.sync sim GEMM + top-3/thread epilogue + flags
//    CTA: 64 m-rows; 16 n-steps of 128; k-chunks of 64 bf16.
//    3-stage cp.async pipeline, ONE __syncthreads per chunk.
// ---------------------------------------------------------------
#define STRIDE   144
#define A_TILE   (64 * STRIDE)         // 9216
#define B_TILE   (128 * STRIDE)        // 18432
#define STAGE    (A_TILE + B_TILE)     // 27648
#define SOFF     8448                  // keep list 8192 + atok 256
#define SMEM_TOT (SOFF + 3 * STAGE)    // 91392

__device__ __forceinline__ void load_stage(int ns, int kc, int sidx, uint32_t sbase,
                                           const int* skeep, const int* satok,
                                           int b, int tid) {
    uint32_t st = sbase + SOFF + (uint32_t)sidx * STAGE;
    int n0 = ns * 128, k0 = kc * 64;                 // 64 bf16 = 128 bytes
    size_t xbase = (size_t)b * T_ * C_ + k0;
    #pragma unroll
    for (int u = 0; u < 2; u++) {                    // A: 64 rows x 8 x 16B
        int i = u * 256 + tid;
        int row = i >> 3, j = i & 7;
        cp16(st + (uint32_t)(row * STRIDE + j * 16),
             g_xbf + xbase + (size_t)satok[row] * C_ + j * 8);
    }
    #pragma unroll
    for (int u = 0; u < 4; u++) {                    // B: 128 rows x 8 x 16B
        int i = u * 256 + tid;
        int row = i >> 3, j = i & 7;
        cp16(st + A_TILE + (uint32_t)(row * STRIDE + j * 16),
             g_xbf + xbase + (size_t)skeep[n0 + row] * C_ + j * 8);
    }
    cp_commit();
}

__global__ void __launch_bounds__(256, 2) simarg_mma() {
    extern __shared__ char smem[];
    uint32_t sbase = smem_u32(smem);
    int* skeep = (int*)smem;            // [2048]
    int* satok = (int*)(smem + 8192);   // [64]
    int tid = threadIdx.x;
    int wid = tid >> 5, lane = tid & 31;
    int wm = wid >> 2, wn = wid & 3;    // warp tile: 32m x 32n
    int b  = blockIdx.y;
    int m0 = blockIdx.x * 64;

    for (int i = tid; i < 2048; i += 256) skeep[i] = g_keep[b * K_ + i];
    if (tid < 64) satok[tid] = g_nonkept[b * NK_ + m0 + tid];
    __syncthreads();

    // ldmatrix lane mappings (non-trans, row/col fragments)
    int arow = (lane & 7) + ((lane >> 3) & 1) * 8;
    int ak8  = (lane >> 4);
    int brow = (lane & 7) + (lane >> 4) * 8;
    int bk8  = (lane >> 3) & 1;

    unsigned long long t0[4], t1[4], t2[4];
    #pragma unroll
    for (int s = 0; s < 4; s++) { t0[s] = 0ull; t1[s] = 0ull; t2[s] = 0ull; }

    // prologue: stages 0 and 1
    load_stage(0, 0, 0, sbase, skeep, satok, b, tid);
    load_stage(0, 1, 1, sbase, skeep, satok, b, tid);

    float acc[2][4][4];
    int g = 0;
    int sidx = 0;                        // g % 3, tracked incrementally
    for (int ns = 0; ns < 16; ns++) {
        #pragma unroll
        for (int mi = 0; mi < 2; mi++)
            #pragma unroll
            for (int ni = 0; ni < 4; ni++)
                #pragma unroll
                for (int r = 0; r < 4; r++) acc[mi][ni][r] = 0.f;

        for (int kc = 0; kc < 16; kc++) {
            // wait for stage g's loads (leave <=1 group pending)
            if (g + 1 < 256) cp_wait1(); else cp_wait0();
            __syncthreads();             // loads visible AND prev compute done
            int gn = g + 2;
            if (gn < 256) {
                int ls = sidx + 2; if (ls >= 3) ls -= 3;
                load_stage(gn >> 4, gn & 15, ls, sbase, skeep, satok, b, tid);
            }

            uint32_t st = sbase + SOFF + (uint32_t)sidx * STAGE;
            #pragma unroll
            for (int q = 0; q < 4; q++) {            // 4 k16 steps per 64-elem chunk
                int kb = q * 32;                     // bytes
                uint32_t ah[2][4], bh[2][4];
                #pragma unroll
                for (int mi = 0; mi < 2; mi++) {
                    uint32_t ra = (uint32_t)((wm * 32 + mi * 16 + arow) * STRIDE
                                             + kb + ak8 * 16);
                    LDSM_X4(ah[mi][0], ah[mi][1], ah[mi][2], ah[mi][3], st + ra);
                }
                #pragma unroll
                for (int nj = 0; nj < 2; nj++) {
                    uint32_t rb = (uint32_t)((wn * 32 + nj * 16 + brow) * STRIDE
                                             + kb + bk8 * 16);
                    LDSM_X4(bh[nj][0], bh[nj][1], bh[nj][2], bh[nj][3], st + A_TILE + rb);
                }
                #pragma unroll
                for (int mi = 0; mi < 2; mi++)
                    #pragma unroll
                    for (int ni = 0; ni < 4; ni++) {
                        int nj = ni >> 1, o = (ni & 1) * 2;
                        MMA16816(acc[mi][ni], ah[mi], bh[nj][o], bh[nj][o + 1]);
                    }
            }
            g++;
            if (++sidx == 3) sidx = 0;
        }

        // fold into per-thread top-3
        #pragma unroll
        for (int mi = 0; mi < 2; mi++)
            #pragma unroll
            for (int h = 0; h < 2; h++) {
                int slot = mi * 2 + h;
                #pragma unroll
                for (int ni = 0; ni < 4; ni++)
                    #pragma unroll
                    for (int cp = 0; cp < 2; cp++) {
                        float v = acc[mi][ni][h * 2 + cp];
                        int col = ns * 128 + wn * 32 + ni * 8 + (lane & 3) * 2 + cp;
                        unsigned long long key =
                            ((unsigned long long)ordf(v) << 32) |
                            (unsigned long long)(0xFFFFFFFFu - (unsigned int)col);
                        if (key > t0[slot]) { t2[slot] = t1[slot]; t1[slot] = t0[slot]; t0[slot] = key; }
                        else if (key > t1[slot]) { t2[slot] = t1[slot]; t1[slot] = key; }
                        else if (key > t2[slot]) t2[slot] = key;
                    }
            }
    }

    // cross-thread merge: 16 groups x 3 entries per row (reuse stage smem)
    unsigned long long* pp = (unsigned long long*)(smem + SOFF);
    __syncthreads();
    #pragma unroll
    for (int slot = 0; slot < 4; slot++) {
        int mi = slot >> 1, h = slot & 1;
        int row = wm * 32 + mi * 16 + h * 8 + (lane >> 2);
        int grp = wn * 4 + (lane & 3);
        pp[row * 48 + grp * 3 + 0] = t0[slot];
        pp[row * 48 + grp * 3 + 1] = t1[slot];
        pp[row * 48 + grp * 3 + 2] = t2[slot];
    }
    __syncthreads();
    if (tid < 64) {
        unsigned long long mx = 0ull;
        for (int e = 0; e < 48; e++) {
            unsigned long long k = pp[tid * 48 + e];
            if (k > mx) mx = k;
        }
        float fmax = iordf((unsigned int)(mx >> 32));
        float thr = fmax - WIN;
        int cnt = 0;
        short cand[NCAND];
        for (int e = 0; e < 48; e++) {
            unsigned long long k = pp[tid * 48 + e];
            if (iordf((unsigned int)(k >> 32)) >= thr) {
                if (cnt < NCAND)
                    cand[cnt] = (short)(0xFFFFFFFFu - (unsigned int)(k & 0xFFFFFFFFull));
                cnt++;
            }
        }
        int tok = satok[tid];
        if (cnt <= 1) {
            g_arg[(size_t)b * T_ + tok] = mx;
        } else {
            int idx = atomicAdd(&g_flagcntb[b], 1);
            g_flagtokb[b][idx] = b * T_ + tok;
            g_flagn[b][idx] = (cnt <= NCAND) ? (unsigned char)cnt : (unsigned char)255;
            for (int j = 0; j < NCAND; j++)
                g_flagcand[b][idx][j] = (j < cnt && cnt <= NCAND) ? cand[j] : 0;
            g_arg[(size_t)b * T_ + tok] = 0ull;   // repair fills
        }
    }
}

// ---------------------------------------------------------------
// 4) exact fp32 re-argmax over candidate columns (or full row).
//    Wider grid (32 sub-blocks per batch) for latency hiding.
// ---------------------------------------------------------------
__global__ void __launch_bounds__(256) repair_kernel(const float* __restrict__ x) {
    int b = blockIdx.x >> 5;
    int sub = blockIdx.x & 31;
    int warp = threadIdx.x >> 5, lane = threadIdx.x & 31;
    int cnt = g_flagcntb[b];
    for (int idx = sub * 8 + warp; idx < cnt; idx += 256) {
        int tok = g_flagtokb[b][idx];         // global token idx
        float tinv = g_invn[tok];
        float4 f[8];
        #pragma unroll
        for (int j = 0; j < 8; j++)
            f[j] = ((const float4*)x)[(size_t)tok * 256 + j * 32 + lane];
        int n = g_flagn[b][idx];
        unsigned long long best = 0ull;
        int iters = (n == 255) ? 2048 : n;
        for (int i = 0; i < iters; i++) {
            int c = (n == 255) ? i : (int)g_flagcand[b][idx][i];
            int ct = g_keep[b * K_ + c];
            const float4* cp = (const float4*)(x + ((size_t)(b * T_ + ct)) * C_);
            float s = 0.f;
            #pragma unroll
            for (int j = 0; j < 8; j++) {
                float4 v = cp[j * 32 + lane];
                s += f[j].x * v.x + f[j].y * v.y + f[j].z * v.z + f[j].w * v.w;
            }
            #pragma unroll
            for (int o = 16; o; o >>= 1) s += __shfl_down_sync(0xffffffffu, s, o);
            if (lane == 0) {
                s *= tinv * g_invn[b * T_ + ct];
                unsigned long long key =
                    ((unsigned long long)ordf(s) << 32) |
                    (unsigned long long)(0xFFFFFFFFu - (unsigned int)c);
                if (key > best) best = key;
            }
        }
        if (lane == 0) g_arg[tok] = best;
    }
}

// ---------------------------------------------------------------
// 5) fused decode + histogram + scan + member-list fill (per batch)
// ---------------------------------------------------------------
__global__ void __launch_bounds__(1024) assign_kernel() {
    int b = blockIdx.x, tid = threadIdx.x;
    __shared__ int hist[2048];
    __shared__ int s0[2048], s1[2048];
    hist[tid] = 0; hist[tid + 1024] = 0;
    __syncthreads();
    int a_[4];
    #pragma unroll
    for (int r = 0; r < 4; r++) {
        int i = b * T_ + r * 1024 + tid;
        int kr = g_keeprank[i];
        int a = (kr >= 0)
            ? kr
            : (int)(0xFFFFFFFFu - (unsigned int)(g_arg[i] & 0xFFFFFFFFull));
        a_[r] = a;
        atomicAdd(&hist[a], 1);
    }
    __syncthreads();
    s0[tid] = hist[tid]; s0[tid + 1024] = hist[tid + 1024];
    __syncthreads();
    int* src = s0; int* dst = s1;
    for (int d = 1; d < 2048; d <<= 1) {
        for (int i = tid; i < 2048; i += 1024) {
            int v = src[i];
            if (i >= d) v += src[i - d];
            dst[i] = v;
        }
        __syncthreads();
        int* t = src; src = dst; dst = t;
    }
    for (int i = tid; i < 2048; i += 1024) {
        int c = hist[i];
        int off = src[i] - c;
        g_off[b * K_ + i] = off;
        g_icnt[b * K_ + i] = c;
        dst[i] = off;                   // cursor (dst buffer is free)
    }
    __syncthreads();
    #pragma unroll
    for (int r = 0; r < 4; r++) {
        int slot = atomicAdd(&dst[a_[r]], 1);
        g_members[b * T_ + slot] = r * 1024 + tid;
    }
}

// ---------------------------------------------------------------
// 6) per-center member sum + blend. Singleton fast path; member
//    loop unrolled x2 (dual accumulators -> MLP 2 on DRAM gather).
// ---------------------------------------------------------------
__global__ void out_kernel(const float* __restrict__ x, float* __restrict__ out) {
    int i = blockIdx.x;                // b*K + k
    int b = i >> 11;
    int tidx = threadIdx.x;
    int cnt = g_icnt[i];
    int ktok = g_keep[i];
    const float4* xk = (const float4*)(x + ((size_t)(b * T_ + ktok)) * C_);
    float4* op = (float4*)out + (size_t)i * 256;
    if (cnt == 1) {                    // merged == x_kept -> blend is identity
        op[tidx] = xk[tidx];
        return;
    }
    int off = g_off[i];
    float4 acc0 = make_float4(0.f, 0.f, 0.f, 0.f);
    float4 acc1 = make_float4(0.f, 0.f, 0.f, 0.f);
    int m = 0;
    for (; m + 1 < cnt; m += 2) {
        int ta = g_members[b * T_ + off + m];
        int tb = g_members[b * T_ + off + m + 1];
        float4 va = ((const float4*)(x + ((size_t)(b * T_ + ta)) * C_))[tidx];
        float4 vb = ((const float4*)(x + ((size_t)(b * T_ + tb)) * C_))[tidx];
        acc0.x += va.x; acc0.y += va.y; acc0.z += va.z; acc0.w += va.w;
        acc1.x += vb.x; acc1.y += vb.y; acc1.z += vb.z; acc1.w += vb.w;
    }
    if (m < cnt) {
        int ta = g_members[b * T_ + off + m];
        float4 va = ((const float4*)(x + ((size_t)(b * T_ + ta)) * C_))[tidx];
        acc0.x += va.x; acc0.y += va.y; acc0.z += va.z; acc0.w += va.w;
    }
    float4 xv = xk[tidx];
    float invc = 1.0f / (float)cnt;
    float4 r;
    r.x = 0.85f * xv.x + 0.15f * (acc0.x + acc1.x) * invc;
    r.y = 0.85f * xv.y + 0.15f * (acc0.y + acc1.y) * invc;
    r.z = 0.85f * xv.z + 0.15f * (acc0.z + acc1.z) * invc;
    r.w = 0.85f * xv.w + 0.15f * (acc0.w + acc1.w) * invc;
    op[tidx] = r;
}

// ---------------------------------------------------------------
extern "C" void kernel_launch(void* const* d_in, const int* in_sizes, int n_in,
                              void* d_out, int out_size) {
    const float* x = (const float*)d_in[0];
    float* out = (float*)d_out;

    cudaFuncSetAttribute(simarg_mma, cudaFuncAttributeMaxDynamicSharedMemorySize, SMEM_TOT);

    scoreq_kernel<<<BT, 256>>>(x);
    topk_kernel<<<B_, 1024>>>();
    {
        dim3 grid(32, B_);
        simarg_mma<<<grid, 256, SMEM_TOT>>>();
    }
    repair_kernel<<<B_ * 32, 256>>>(x);
    assign_kernel<<<B_, 1024>>>();
    out_kernel<<<BK, 256>>>(x, out);
}

// round 17
// speedup vs baseline: 1.0493x; 1.0493x over previous
#include <cuda_runtime.h>
#include <cuda_bf16.h>
#include <cstdint>
#include <math.h>

#define B_   8
#define T_   4096
#define C_   1024
#define K_   2048
#define NK_  2048
#define BT   (B_ * T_)
#define BK   (B_ * K_)

#define FLAG_CAP 4096
#define WIN      1e-3f      // candidate window: 2x max bf16 sim error, with margin
#define NCAND    8

// ---- scratch (__device__ globals: allocation-free) ----
__device__ float  g_score[BT];
__device__ float  g_invn[BT];
__device__ int    g_keep[BK];
__device__ int    g_nonkept[B_ * NK_];
__device__ int    g_keeprank[BT];
__device__ unsigned long long g_arg[BT];
__device__ int    g_icnt[BK];
__device__ int    g_off[BK];
__device__ int    g_members[BT];
__device__ int    g_flagcntb[B_];
__device__ int    g_flagtokb[B_][FLAG_CAP];
__device__ unsigned char g_flagn[B_][FLAG_CAP];
__device__ short  g_flagcand[B_][FLAG_CAP][NCAND];
__device__ __nv_bfloat16 g_xbf[(size_t)BT * C_];   // 64 MB normalized bf16 tokens

__device__ __forceinline__ unsigned int ordf(float f) {
    unsigned int u = __float_as_uint(f);
    return (u & 0x80000000u) ? ~u : (u | 0x80000000u);
}
__device__ __forceinline__ float iordf(unsigned int u) {
    return __uint_as_float((u & 0x80000000u) ? (u & 0x7FFFFFFFu) : ~u);
}

// =====================  async-copy / mma helpers  =====================
__device__ __forceinline__ uint32_t smem_u32(const void* p) {
    uint32_t a;
    asm("{ .reg .u64 t; cvta.to.shared.u64 t, %1; cvt.u32.u64 %0, t; }" : "=r"(a) : "l"(p));
    return a;
}
__device__ __forceinline__ void cp16(uint32_t dst, const void* src) {
    asm volatile("cp.async.cg.shared.global [%0], [%1], 16;" :: "r"(dst), "l"(src) : "memory");
}
__device__ __forceinline__ void cp_commit() { asm volatile("cp.async.commit_group;" ::: "memory"); }
__device__ __forceinline__ void cp_wait1()  { asm volatile("cp.async.wait_group 1;" ::: "memory"); }
__device__ __forceinline__ void cp_wait0()  { asm volatile("cp.async.wait_group 0;" ::: "memory"); }

#define LDSM_X4(r0, r1, r2, r3, addr) \
    asm volatile("ldmatrix.sync.aligned.m8n8.x4.shared.b16 {%0,%1,%2,%3}, [%4];" \
        : "=r"(r0), "=r"(r1), "=r"(r2), "=r"(r3) : "r"(addr))
#define MMA16816(c, a, b0, b1) \
    asm volatile("mma.sync.aligned.m16n8k16.row.col.f32.bf16.bf16.f32 " \
        "{%0,%1,%2,%3}, {%4,%5,%6,%7}, {%8,%9}, {%0,%1,%2,%3};" \
        : "+f"((c)[0]), "+f"((c)[1]), "+f"((c)[2]), "+f"((c)[3]) \
        : "r"((a)[0]), "r"((a)[1]), "r"((a)[2]), "r"((a)[3]), "r"(b0), "r"(b1))

// ---------------------------------------------------------------
// 1) fused: per-token L2 score + inverse norm + normalized bf16.
//    128 threads, 2 float4s each; per-float4 int64 fixed-point
//    partials keep the reduction bit-identical to the 256-thr ver.
// ---------------------------------------------------------------
__global__ void __launch_bounds__(128) scoreq_kernel(const float* __restrict__ x) {
    int tok = blockIdx.x;
    const float4* xp = (const float4*)(x + (size_t)tok * C_);
    float4 v0 = xp[threadIdx.x];
    float4 v1 = xp[threadIdx.x + 128];
    float p0 = fmaf(v0.x, v0.x, fmaf(v0.y, v0.y, fmaf(v0.z, v0.z, v0.w * v0.w)));
    float p1 = fmaf(v1.x, v1.x, fmaf(v1.y, v1.y, fmaf(v1.z, v1.z, v1.w * v1.w)));
    long long q = __float2ll_rn(p0 * 16777216.0f) + __float2ll_rn(p1 * 16777216.0f);
    #pragma unroll
    for (int o = 16; o; o >>= 1) q += __shfl_down_sync(0xffffffffu, q, o);
    __shared__ long long sm[4];
    __shared__ float binv;
    if ((threadIdx.x & 31) == 0) sm[threadIdx.x >> 5] = q;
    __syncthreads();
    if (threadIdx.x == 0) {
        long long tq = sm[0] + sm[1] + sm[2] + sm[3];
        double ss = (double)tq * (1.0 / 16777216.0);
        float fs = (float)ss;
        if ((tok & (T_ - 1)) == 0) fs = 3.402823466e+38f;   // CLS protection
        g_score[tok] = fs;
        float invn = (float)(1.0 / (sqrt(ss) + 1e-12));
        g_invn[tok] = invn;
        binv = invn;
    }
    __syncthreads();
    float inv = binv;
    uint2* dst = (uint2*)(g_xbf + (size_t)tok * C_);
    __nv_bfloat162 a0 = __halves2bfloat162(__float2bfloat16(v0.x * inv),
                                           __float2bfloat16(v0.y * inv));
    __nv_bfloat162 a1 = __halves2bfloat162(__float2bfloat16(v0.z * inv),
                                           __float2bfloat16(v0.w * inv));
    dst[threadIdx.x] = make_uint2(*(unsigned int*)&a0, *(unsigned int*)&a1);
    __nv_bfloat162 b0 = __halves2bfloat162(__float2bfloat16(v1.x * inv),
                                           __float2bfloat16(v1.y * inv));
    __nv_bfloat162 b1 = __halves2bfloat162(__float2bfloat16(v1.z * inv),
                                           __float2bfloat16(v1.w * inv));
    dst[threadIdx.x + 128] = make_uint2(*(unsigned int*)&b0, *(unsigned int*)&b1);
}

// ---------------------------------------------------------------
// 2) per-batch exact top-K via 64-bit radix select + ordered
//    compaction (keys unique -> exact bound; token-order output).
// ---------------------------------------------------------------
__global__ void __launch_bounds__(1024) topk_kernel() {
    int b = blockIdx.x, tid = threadIdx.x;
    __shared__ unsigned long long skey[T_];     // token-order keys, 32KB
    __shared__ int hist[4][256];                // sub-histograms, 4KB
    __shared__ int sscan[1024];
    __shared__ unsigned long long sh_pref, sh_bound;
    __shared__ int sh_r, sh_done;

    if (tid == 0) { g_flagcntb[b] = 0; sh_pref = 0ull; sh_r = K_; sh_done = 0; }
    #pragma unroll
    for (int j = 0; j < 4; j++) {
        int i = tid * 4 + j;
        skey[i] = ((unsigned long long)(~ordf(g_score[b * T_ + i])) << 32)
                | (unsigned int)i;
    }
    __syncthreads();

    // byte-wise descent from MSB
    unsigned long long hi_mask = 0ull;
    int hsub = (tid >> 5) & 3;
    for (int byte = 7; byte >= 0; byte--) {
        if (sh_done) break;                      // uniform (smem, post-sync)
        int shift = byte * 8;
        ((int*)hist)[tid] = 0;
        __syncthreads();
        unsigned long long pref = sh_pref;
        #pragma unroll
        for (int j = 0; j < 4; j++) {
            unsigned long long k = skey[tid * 4 + j];
            if ((k & hi_mask) == pref)
                atomicAdd(&hist[hsub][(int)((k >> shift) & 255)], 1);
        }
        __syncthreads();
        if (tid == 0) {
            int r = sh_r, cum = 0;
            for (int bin = 0; bin < 256; bin++) {
                int c = hist[0][bin] + hist[1][bin] + hist[2][bin] + hist[3][bin];
                if (cum + c >= r) {
                    if (cum + c == r) {
                        sh_bound = (bin == 255 && shift == 56)
                                 ? ~0ull
                                 : pref + ((unsigned long long)(bin + 1) << shift);
                        sh_done = 1;
                    } else {
                        sh_pref = pref | ((unsigned long long)bin << shift);
                        sh_r = r - cum;
                    }
                    break;
                }
                cum += c;
            }
        }
        hi_mask |= (0xFFull << shift);
        __syncthreads();
    }
    if (tid == 0 && !sh_done) sh_bound = sh_pref + 1ull;  // exact key (unique)
    __syncthreads();
    unsigned long long bound = sh_bound;

    // token-order compaction
    int cnt = 0;
    #pragma unroll
    for (int j = 0; j < 4; j++) cnt += (skey[tid * 4 + j] < bound) ? 1 : 0;
    sscan[tid] = cnt;
    __syncthreads();
    for (int d = 1; d < 1024; d <<= 1) {
        int v = sscan[tid];
        int add = (tid >= d) ? sscan[tid - d] : 0;
        __syncthreads();
        sscan[tid] = v + add;
        __syncthreads();
    }
    int kpos = sscan[tid] - cnt;                 // keeps strictly before my tokens
    #pragma unroll
    for (int j = 0; j < 4; j++) {
        int i = tid * 4 + j;
        if (skey[i] < bound) {
            g_keep[b * K_ + kpos] = i;
            g_keeprank[b * T_ + i] = kpos;
            kpos++;
        } else {
            g_nonkept[b * NK_ + (i - kpos)] = i;
            g_keeprank[b * T_ + i] = -1;
        }
    }
}

// ---------------------------------------------------------------
// 3) bf16 mma.sync sim GEMM + top-3/thread epilogue + flags
//    CTA: 64 m-rows; 16 n-steps of 128; k-chunks of 64 bf16.
//    3-stage cp.async pipeline, ONE __syncthreads per chunk.
// ---------------------------------------------------------------
#define STRIDE   144
#define A_TILE   (64 * STRIDE)         // 9216
#define B_TILE   (128 * STRIDE)        // 18432
#define STAGE    (A_TILE + B_TILE)     // 27648
#define SOFF     8448                  // keep list 8192 + atok 256
#define SMEM_TOT (SOFF + 3 * STAGE)    // 91392

__device__ __forceinline__ void load_stage(int ns, int kc, int sidx, uint32_t sbase,
                                           const int* skeep, const int* satok,
                                           int b, int tid) {
    uint32_t st = sbase + SOFF + (uint32_t)sidx * STAGE;
    int n0 = ns * 128, k0 = kc * 64;                 // 64 bf16 = 128 bytes
    size_t xbase = (size_t)b * T_ * C_ + k0;
    #pragma unroll
    for (int u = 0; u < 2; u++) {                    // A: 64 rows x 8 x 16B
        int i = u * 256 + tid;
        int row = i >> 3, j = i & 7;
        cp16(st + (uint32_t)(row * STRIDE + j * 16),
             g_xbf + xbase + (size_t)satok[row] * C_ + j * 8);
    }
    #pragma unroll
    for (int u = 0; u < 4; u++) {                    // B: 128 rows x 8 x 16B
        int i = u * 256 + tid;
        int row = i >> 3, j = i & 7;
        cp16(st + A_TILE + (uint32_t)(row * STRIDE + j * 16),
             g_xbf + xbase + (size_t)skeep[n0 + row] * C_ + j * 8);
    }
    cp_commit();
}

__global__ void __launch_bounds__(256, 2) simarg_mma() {
    extern __shared__ char smem[];
    uint32_t sbase = smem_u32(smem);
    int* skeep = (int*)smem;            // [2048]
    int* satok = (int*)(smem + 8192);   // [64]
    int tid = threadIdx.x;
    int wid = tid >> 5, lane = tid & 31;
    int wm = wid >> 2, wn = wid & 3;    // warp tile: 32m x 32n
    int b  = blockIdx.y;
    int m0 = blockIdx.x * 64;

    for (int i = tid; i < 2048; i += 256) skeep[i] = g_keep[b * K_ + i];
    if (tid < 64) satok[tid] = g_nonkept[b * NK_ + m0 + tid];
    __syncthreads();

    // ldmatrix lane mappings (non-trans, row/col fragments)
    int arow = (lane & 7) + ((lane >> 3) & 1) * 8;
    int ak8  = (lane >> 4);
    int brow = (lane & 7) + (lane >> 4) * 8;
    int bk8  = (lane >> 3) & 1;

    unsigned long long t0[4], t1[4], t2[4];
    #pragma unroll
    for (int s = 0; s < 4; s++) { t0[s] = 0ull; t1[s] = 0ull; t2[s] = 0ull; }

    // prologue: stages 0 and 1
    load_stage(0, 0, 0, sbase, skeep, satok, b, tid);
    load_stage(0, 1, 1, sbase, skeep, satok, b, tid);

    float acc[2][4][4];
    int g = 0;
    int sidx = 0;                        // g % 3, tracked incrementally
    for (int ns = 0; ns < 16; ns++) {
        #pragma unroll
        for (int mi = 0; mi < 2; mi++)
            #pragma unroll
            for (int ni = 0; ni < 4; ni++)
                #pragma unroll
                for (int r = 0; r < 4; r++) acc[mi][ni][r] = 0.f;

        for (int kc = 0; kc < 16; kc++) {
            // wait for stage g's loads (leave <=1 group pending)
            if (g + 1 < 256) cp_wait1(); else cp_wait0();
            __syncthreads();             // loads visible AND prev compute done
            int gn = g + 2;
            if (gn < 256) {
                int ls = sidx + 2; if (ls >= 3) ls -= 3;
                load_stage(gn >> 4, gn & 15, ls, sbase, skeep, satok, b, tid);
            }

            uint32_t st = sbase + SOFF + (uint32_t)sidx * STAGE;
            #pragma unroll
            for (int q = 0; q < 4; q++) {            // 4 k16 steps per 64-elem chunk
                int kb = q * 32;                     // bytes
                uint32_t ah[2][4], bh[2][4];
                #pragma unroll
                for (int mi = 0; mi < 2; mi++) {
                    uint32_t ra = (uint32_t)((wm * 32 + mi * 16 + arow) * STRIDE
                                             + kb + ak8 * 16);
                    LDSM_X4(ah[mi][0], ah[mi][1], ah[mi][2], ah[mi][3], st + ra);
                }
                #pragma unroll
                for (int nj = 0; nj < 2; nj++) {
                    uint32_t rb = (uint32_t)((wn * 32 + nj * 16 + brow) * STRIDE
                                             + kb + bk8 * 16);
                    LDSM_X4(bh[nj][0], bh[nj][1], bh[nj][2], bh[nj][3], st + A_TILE + rb);
                }
                #pragma unroll
                for (int mi = 0; mi < 2; mi++)
                    #pragma unroll
                    for (int ni = 0; ni < 4; ni++) {
                        int nj = ni >> 1, o = (ni & 1) * 2;
                        MMA16816(acc[mi][ni], ah[mi], bh[nj][o], bh[nj][o + 1]);
                    }
            }
            g++;
            if (++sidx == 3) sidx = 0;
        }

        // fold into per-thread top-3
        #pragma unroll
        for (int mi = 0; mi < 2; mi++)
            #pragma unroll
            for (int h = 0; h < 2; h++) {
                int slot = mi * 2 + h;
                #pragma unroll
                for (int ni = 0; ni < 4; ni++)
                    #pragma unroll
                    for (int cp = 0; cp < 2; cp++) {
                        float v = acc[mi][ni][h * 2 + cp];
                        int col = ns * 128 + wn * 32 + ni * 8 + (lane & 3) * 2 + cp;
                        unsigned long long key =
                            ((unsigned long long)ordf(v) << 32) |
                            (unsigned long long)(0xFFFFFFFFu - (unsigned int)col);
                        if (key > t0[slot]) { t2[slot] = t1[slot]; t1[slot] = t0[slot]; t0[slot] = key; }
                        else if (key > t1[slot]) { t2[slot] = t1[slot]; t1[slot] = key; }
                        else if (key > t2[slot]) t2[slot] = key;
                    }
            }
    }

    // cross-thread merge: 16 groups x 3 entries per row (reuse stage smem)
    unsigned long long* pp = (unsigned long long*)(smem + SOFF);
    __syncthreads();
    #pragma unroll
    for (int slot = 0; slot < 4; slot++) {
        int mi = slot >> 1, h = slot & 1;
        int row = wm * 32 + mi * 16 + h * 8 + (lane >> 2);
        int grp = wn * 4 + (lane & 3);
        pp[row * 48 + grp * 3 + 0] = t0[slot];
        pp[row * 48 + grp * 3 + 1] = t1[slot];
        pp[row * 48 + grp * 3 + 2] = t2[slot];
    }
    __syncthreads();
    if (tid < 64) {
        unsigned long long mx = 0ull;
        for (int e = 0; e < 48; e++) {
            unsigned long long k = pp[tid * 48 + e];
            if (k > mx) mx = k;
        }
        float fmax = iordf((unsigned int)(mx >> 32));
        float thr = fmax - WIN;
        int cnt = 0;
        short cand[NCAND];
        for (int e = 0; e < 48; e++) {
            unsigned long long k = pp[tid * 48 + e];
            if (iordf((unsigned int)(k >> 32)) >= thr) {
                if (cnt < NCAND)
                    cand[cnt] = (short)(0xFFFFFFFFu - (unsigned int)(k & 0xFFFFFFFFull));
                cnt++;
            }
        }
        int tok = satok[tid];
        if (cnt <= 1) {
            g_arg[(size_t)b * T_ + tok] = mx;
        } else {
            int idx = atomicAdd(&g_flagcntb[b], 1);
            g_flagtokb[b][idx] = b * T_ + tok;
            g_flagn[b][idx] = (cnt <= NCAND) ? (unsigned char)cnt : (unsigned char)255;
            for (int j = 0; j < NCAND; j++)
                g_flagcand[b][idx][j] = (j < cnt && cnt <= NCAND) ? cand[j] : 0;
            g_arg[(size_t)b * T_ + tok] = 0ull;   // repair fills
        }
    }
}

// ---------------------------------------------------------------
// 4) exact fp32 re-argmax over candidate columns (or full row).
// ---------------------------------------------------------------
__global__ void __launch_bounds__(256) repair_kernel(const float* __restrict__ x) {
    int b = blockIdx.x >> 5;
    int sub = blockIdx.x & 31;
    int warp = threadIdx.x >> 5, lane = threadIdx.x & 31;
    int cnt = g_flagcntb[b];
    for (int idx = sub * 8 + warp; idx < cnt; idx += 256) {
        int tok = g_flagtokb[b][idx];         // global token idx
        float tinv = g_invn[tok];
        float4 f[8];
        #pragma unroll
        for (int j = 0; j < 8; j++)
            f[j] = ((const float4*)x)[(size_t)tok * 256 + j * 32 + lane];
        int n = g_flagn[b][idx];
        unsigned long long best = 0ull;
        int iters = (n == 255) ? 2048 : n;
        for (int i = 0; i < iters; i++) {
            int c = (n == 255) ? i : (int)g_flagcand[b][idx][i];
            int ct = g_keep[b * K_ + c];
            const float4* cp = (const float4*)(x + ((size_t)(b * T_ + ct)) * C_);
            float s = 0.f;
            #pragma unroll
            for (int j = 0; j < 8; j++) {
                float4 v = cp[j * 32 + lane];
                s += f[j].x * v.x + f[j].y * v.y + f[j].z * v.z + f[j].w * v.w;
            }
            #pragma unroll
            for (int o = 16; o; o >>= 1) s += __shfl_down_sync(0xffffffffu, s, o);
            if (lane == 0) {
                s *= tinv * g_invn[b * T_ + ct];
                unsigned long long key =
                    ((unsigned long long)ordf(s) << 32) |
                    (unsigned long long)(0xFFFFFFFFu - (unsigned int)c);
                if (key > best) best = key;
            }
        }
        if (lane == 0) g_arg[tok] = best;
    }
}

// ---------------------------------------------------------------
// 5) fused decode + histogram + scan + member-list fill (per batch)
// ---------------------------------------------------------------
__global__ void __launch_bounds__(1024) assign_kernel() {
    int b = blockIdx.x, tid = threadIdx.x;
    __shared__ int hist[2048];
    __shared__ int s0[2048], s1[2048];
    hist[tid] = 0; hist[tid + 1024] = 0;
    __syncthreads();
    int a_[4];
    #pragma unroll
    for (int r = 0; r < 4; r++) {
        int i = b * T_ + r * 1024 + tid;
        int kr = g_keeprank[i];
        int a = (kr >= 0)
            ? kr
            : (int)(0xFFFFFFFFu - (unsigned int)(g_arg[i] & 0xFFFFFFFFull));
        a_[r] = a;
        atomicAdd(&hist[a], 1);
    }
    __syncthreads();
    s0[tid] = hist[tid]; s0[tid + 1024] = hist[tid + 1024];
    __syncthreads();
    int* src = s0; int* dst = s1;
    for (int d = 1; d < 2048; d <<= 1) {
        for (int i = tid; i < 2048; i += 1024) {
            int v = src[i];
            if (i >= d) v += src[i - d];
            dst[i] = v;
        }
        __syncthreads();
        int* t = src; src = dst; dst = t;
    }
    for (int i = tid; i < 2048; i += 1024) {
        int c = hist[i];
        int off = src[i] - c;
        g_off[b * K_ + i] = off;
        g_icnt[b * K_ + i] = c;
        dst[i] = off;                   // cursor (dst buffer is free)
    }
    __syncthreads();
    #pragma unroll
    for (int r = 0; r < 4; r++) {
        int slot = atomicAdd(&dst[a_[r]], 1);
        g_members[b * T_ + slot] = r * 1024 + tid;
    }
}

// ---------------------------------------------------------------
// 6) per-center member sum + blend. 128 threads, 2 float4s each
//    (MLP 2 on the gather, denser block packing). Singleton fast
//    path: cnt==1 -> out = x_kept exactly.
// ---------------------------------------------------------------
__global__ void __launch_bounds__(128) out_kernel(const float* __restrict__ x,
                                                  float* __restrict__ out) {
    int i = blockIdx.x;                // b*K + k
    int b = i >> 11;
    int tidx = threadIdx.x;
    int cnt = g_icnt[i];
    int ktok = g_keep[i];
    const float4* xk = (const float4*)(x + ((size_t)(b * T_ + ktok)) * C_);
    float4* op = (float4*)out + (size_t)i * 256;
    if (cnt == 1) {                    // merged == x_kept -> blend is identity
        op[tidx] = xk[tidx];
        op[tidx + 128] = xk[tidx + 128];
        return;
    }
    int off = g_off[i];
    float4 acc0 = make_float4(0.f, 0.f, 0.f, 0.f);
    float4 acc1 = make_float4(0.f, 0.f, 0.f, 0.f);
    for (int m = 0; m < cnt; m++) {
        int ta = g_members[b * T_ + off + m];
        const float4* vp = (const float4*)(x + ((size_t)(b * T_ + ta)) * C_);
        float4 va = vp[tidx];
        float4 vb = vp[tidx + 128];
        acc0.x += va.x; acc0.y += va.y; acc0.z += va.z; acc0.w += va.w;
        acc1.x += vb.x; acc1.y += vb.y; acc1.z += vb.z; acc1.w += vb.w;
    }
    float invc = 1.0f / (float)cnt;
    float4 xv0 = xk[tidx], xv1 = xk[tidx + 128];
    float4 r0, r1;
    r0.x = 0.85f * xv0.x + 0.15f * acc0.x * invc;
    r0.y = 0.85f * xv0.y + 0.15f * acc0.y * invc;
    r0.z = 0.85f * xv0.z + 0.15f * acc0.z * invc;
    r0.w = 0.85f * xv0.w + 0.15f * acc0.w * invc;
    r1.x = 0.85f * xv1.x + 0.15f * acc1.x * invc;
    r1.y = 0.85f * xv1.y + 0.15f * acc1.y * invc;
    r1.z = 0.85f * xv1.z + 0.15f * acc1.z * invc;
    r1.w = 0.85f * xv1.w + 0.15f * acc1.w * invc;
    op[tidx] = r0;
    op[tidx + 128] = r1;
}

// ---------------------------------------------------------------
extern "C" void kernel_launch(void* const* d_in, const int* in_sizes, int n_in,
                              void* d_out, int out_size) {
    const float* x = (const float*)d_in[0];
    float* out = (float*)d_out;

    cudaFuncSetAttribute(simarg_mma, cudaFuncAttributeMaxDynamicSharedMemorySize, SMEM_TOT);

    scoreq_kernel<<<BT, 128>>>(x);
    topk_kernel<<<B_, 1024>>>();
    {
        dim3 grid(32, B_);
        simarg_mma<<<grid, 256, SMEM_TOT>>>();
    }
    repair_kernel<<<B_ * 32, 256>>>(x);
    assign_kernel<<<B_, 1024>>>();
    out_kernel<<<BK, 128>>>(x, out);
}